// round 6
// baseline (speedup 1.0000x reference)
#include <cuda_runtime.h>

#define BB 8
#define HH 512
#define WW 512
#define HW (HH * WW)

#define TX 32
#define PY 8
#define TYW 4
#define TILE_H (PY * TYW)   // 32
#define SW (TX + 6)         // 38
#define SH (TILE_H + 6)     // 38
#define NBLOCKS ((WW / TX) * (HH / TILE_H) * BB)  // 2048

__device__ int g_total = 0;
__device__ unsigned int g_done = 0;

__global__ __launch_bounds__(TX * TYW, 10)
void census_fused(const float* __restrict__ pred, const float* __restrict__ tgt,
                  float* __restrict__ out) {
    __shared__ float2 s[SH][SW];      // (pred_gray, tgt_gray) interleaved
    __shared__ int wsum[TYW];

    const int b  = blockIdx.z;
    const int x0 = blockIdx.x * TX;
    const int y0 = blockIdx.y * TILE_H;
    const int tid = threadIdx.y * TX + threadIdx.x;

    const float* __restrict__ pb = pred + (size_t)b * 3 * HW;
    const float* __restrict__ tb = tgt  + (size_t)b * 3 * HW;

    // Halo load + fused RGB->gray, reflect padding (no edge repeat)
    for (int idx = tid; idx < SH * SW; idx += TX * TYW) {
        int ly = idx / SW;
        int lx = idx - ly * SW;
        int gy = y0 + ly - 3;
        gy = (gy < 0) ? -gy : ((gy >= HH) ? 2 * HH - 2 - gy : gy);
        int gx = x0 + lx - 3;
        gx = (gx < 0) ? -gx : ((gx >= WW) ? 2 * WW - 2 - gx : gx);
        int off = gy * WW + gx;
        float2 v;
        v.x = fmaf(0.299f, pb[off], fmaf(0.587f, pb[HW + off], 0.114f * pb[2 * HW + off]));
        v.y = fmaf(0.299f, tb[off], fmaf(0.587f, tb[HW + off], 0.114f * tb[2 * HW + off]));
        s[ly][lx] = v;
    }
    __syncthreads();

    const int tx   = threadIdx.x;
    const int base = threadIdx.y * PY;

    float cp[PY], ct[PY];
#pragma unroll
    for (int k = 0; k < PY; k++) {
        float2 c = s[base + k + 3][tx + 3];
        cp[k] = c.x; ct[k] = c.y;
    }

    int total;
    const bool interiorBlk = (blockIdx.x > 0 && blockIdx.x + 1 < gridDim.x &&
                              blockIdx.y > 0 && blockIdx.y + 1 < gridDim.y);
    if (interiorBlk) {
        // All pixels >=3 from image border: 24 forward offsets, counted x2.
        // 4 independent accumulators to break the predicated-IADD chain.
        int acc0 = 0, acc1 = 0, acc2 = 0, acc3 = 0;
#pragma unroll
        for (int r = 3; r <= 13; r++) {
            float2 v[7];
#pragma unroll
            for (int j = 0; j < 7; j++) v[j] = s[base + r][tx + j];
            int c = 0;
            {   // dy == 0, dx = 1..3
                const int k = r - 3;
                if (k < PY) {
#pragma unroll
                    for (int j = 4; j < 7; j++)
                        c += ((cp[k] > v[j].x) != (ct[k] > v[j].y)) ? 1 : 0;
                }
            }
#pragma unroll
            for (int dy = 1; dy <= 3; dy++) {   // dy = 1..3, all dx
                const int k = r - 3 - dy;
                if (k >= 0 && k < PY) {
#pragma unroll
                    for (int j = 0; j < 7; j++)
                        c += ((cp[k] > v[j].x) != (ct[k] > v[j].y)) ? 1 : 0;
                }
            }
            switch (r & 3) {
                case 0: acc0 += c; break;
                case 1: acc1 += c; break;
                case 2: acc2 += c; break;
                default: acc3 += c; break;
            }
        }
        total = 2 * ((acc0 + acc1) + (acc2 + acc3));
    } else {
        // Weighted exact path:
        //   target in-image : fwd x2, bwd x0
        //   target out      : x1 (reflected value already in smem)
        unsigned oxm = 0;
#pragma unroll
        for (int j = 0; j < 7; j++)
            if ((unsigned)(x0 + tx + j - 3) >= WW) oxm |= (1u << j);

        int acc0 = 0, acc1 = 0;
#pragma unroll
        for (int r = 0; r < 14; r++) {
            const int oy = ((unsigned)(y0 + base + r - 3) >= HH) ? 1 : 0;
            float2 v[7];
#pragma unroll
            for (int j = 0; j < 7; j++) v[j] = s[base + r][tx + j];
#pragma unroll
            for (int k = 0; k < PY; k++) {
                const int dy = r - 3 - k;
                if (dy < -3 || dy > 3) continue;   // compile-time pruned
#pragma unroll
                for (int j = 0; j < 7; j++) {
                    const int dx = j - 3;
                    if (dy == 0 && dx == 0) continue;
                    int o = oy | (int)((oxm >> j) & 1u);
                    const bool fwd = (dy > 0) || (dy == 0 && dx > 0);
                    int w = fwd ? (2 - o) : o;
                    int m = ((cp[k] > v[j].x) != (ct[k] > v[j].y)) ? 1 : 0;
                    if (r & 1) acc1 += m * w; else acc0 += m * w;
                }
            }
        }
        total = acc0 + acc1;
    }

    // Warp reduction (REDUX) + block reduction
    total = __reduce_add_sync(0xffffffffu, total);
    if (tx == 0) wsum[threadIdx.y] = total;
    __syncthreads();

    if (tid == 0) {
        int v = wsum[0] + wsum[1] + wsum[2] + wsum[3];
        atomicAdd(&g_total, v);
        __threadfence();
        unsigned int ticket = atomicAdd(&g_done, 1u);
        if (ticket == NBLOCKS - 1) {
            int tot = atomicAdd(&g_total, 0);
            const double denom = 48.0 * (double)BB * (double)HW; // 100663296
            out[0] = (float)((double)tot / denom);
            atomicExch(&g_total, 0);      // reset for next graph replay
            atomicExch(&g_done, 0u);
        }
    }
}

extern "C" void kernel_launch(void* const* d_in, const int* in_sizes, int n_in,
                              void* d_out, int out_size) {
    const float* pred = (const float*)d_in[0];
    const float* tgt  = (const float*)d_in[1];
    float* out = (float*)d_out;
    (void)in_sizes; (void)n_in; (void)out_size;

    dim3 bdim(TX, TYW);
    dim3 gdim(WW / TX, HH / TILE_H, BB);
    census_fused<<<gdim, bdim>>>(pred, tgt, out);
}

// round 7
// speedup vs baseline: 1.1627x; 1.1627x over previous
#include <cuda_runtime.h>

#define BB 8
#define HH 512
#define WW 512
#define HW (HH * WW)

#define TX 32
#define PY 4
#define TYW 8
#define TILE_H (PY * TYW)   // 32
#define SW (TX + 6)         // 38
#define SH (TILE_H + 6)     // 38
#define NBLOCKS ((WW / TX) * (HH / TILE_H) * BB)  // 2048

__device__ int g_total = 0;
__device__ unsigned int g_done = 0;

__global__ __launch_bounds__(TX * TYW, 6)
void census_fused(const float* __restrict__ pred, const float* __restrict__ tgt,
                  float* __restrict__ out) {
    __shared__ float2 s[SH][SW];      // (pred_gray, tgt_gray) interleaved
    __shared__ int wsum[TYW];

    const int b  = blockIdx.z;
    const int x0 = blockIdx.x * TX;
    const int y0 = blockIdx.y * TILE_H;
    const int tid = threadIdx.y * TX + threadIdx.x;

    const float* __restrict__ pb = pred + (size_t)b * 3 * HW;
    const float* __restrict__ tb = tgt  + (size_t)b * 3 * HW;

    // Halo load + fused RGB->gray, reflect padding (no edge repeat)
    for (int idx = tid; idx < SH * SW; idx += TX * TYW) {
        int ly = idx / SW;
        int lx = idx - ly * SW;
        int gy = y0 + ly - 3;
        gy = (gy < 0) ? -gy : ((gy >= HH) ? 2 * HH - 2 - gy : gy);
        int gx = x0 + lx - 3;
        gx = (gx < 0) ? -gx : ((gx >= WW) ? 2 * WW - 2 - gx : gx);
        int off = gy * WW + gx;
        float2 v;
        v.x = fmaf(0.299f, pb[off], fmaf(0.587f, pb[HW + off], 0.114f * pb[2 * HW + off]));
        v.y = fmaf(0.299f, tb[off], fmaf(0.587f, tb[HW + off], 0.114f * tb[2 * HW + off]));
        s[ly][lx] = v;
    }
    __syncthreads();

    const int tx   = threadIdx.x;
    const int base = threadIdx.y * PY;

    float cp[PY], ct[PY];
#pragma unroll
    for (int k = 0; k < PY; k++) {
        float2 c = s[base + k + 3][tx + 3];
        cp[k] = c.x; ct[k] = c.y;
    }

    int total;
    const bool interiorBlk = (blockIdx.x > 0 && blockIdx.x + 1 < gridDim.x &&
                              blockIdx.y > 0 && blockIdx.y + 1 < gridDim.y);
    if (interiorBlk) {
        // All pixels >=3 from image border: 24 forward offsets, counted x2.
        int acc0 = 0, acc1 = 0;
#pragma unroll
        for (int r = 3; r <= 9; r++) {            // window rows 3 .. PY+5
            float2 v[7];
#pragma unroll
            for (int j = 0; j < 7; j++) v[j] = s[base + r][tx + j];
            int c = 0;
            {   // dy == 0, dx = 1..3
                const int k = r - 3;
                if (k < PY) {
#pragma unroll
                    for (int j = 4; j < 7; j++)
                        c += ((cp[k] > v[j].x) != (ct[k] > v[j].y)) ? 1 : 0;
                }
            }
#pragma unroll
            for (int dy = 1; dy <= 3; dy++) {
                const int k = r - 3 - dy;
                if (k >= 0 && k < PY) {
#pragma unroll
                    for (int j = 0; j < 7; j++)
                        c += ((cp[k] > v[j].x) != (ct[k] > v[j].y)) ? 1 : 0;
                }
            }
            if (r & 1) acc1 += c; else acc0 += c;
        }
        total = 2 * (acc0 + acc1);
    } else {
        // Weighted exact path:
        //   target in-image : fwd x2, bwd x0
        //   target out      : x1 (reflected value already in smem)
        unsigned oxm = 0;
#pragma unroll
        for (int j = 0; j < 7; j++)
            if ((unsigned)(x0 + tx + j - 3) >= WW) oxm |= (1u << j);

        int acc0 = 0, acc1 = 0;
#pragma unroll
        for (int r = 0; r < PY + 6; r++) {        // 10 rows
            const int oy = ((unsigned)(y0 + base + r - 3) >= HH) ? 1 : 0;
            float2 v[7];
#pragma unroll
            for (int j = 0; j < 7; j++) v[j] = s[base + r][tx + j];
#pragma unroll
            for (int k = 0; k < PY; k++) {
                const int dy = r - 3 - k;
                if (dy < -3 || dy > 3) continue;   // compile-time pruned
#pragma unroll
                for (int j = 0; j < 7; j++) {
                    const int dx = j - 3;
                    if (dy == 0 && dx == 0) continue;
                    int o = oy | (int)((oxm >> j) & 1u);
                    const bool fwd = (dy > 0) || (dy == 0 && dx > 0);
                    int w = fwd ? (2 - o) : o;
                    int m = ((cp[k] > v[j].x) != (ct[k] > v[j].y)) ? 1 : 0;
                    if (r & 1) acc1 += m * w; else acc0 += m * w;
                }
            }
        }
        total = acc0 + acc1;
    }

    // Warp reduction (REDUX) + block reduction
    total = __reduce_add_sync(0xffffffffu, total);
    if (tx == 0) wsum[threadIdx.y] = total;
    __syncthreads();

    if (tid == 0) {
        int v = 0;
#pragma unroll
        for (int w = 0; w < TYW; w++) v += wsum[w];
        atomicAdd(&g_total, v);
        __threadfence();
        unsigned int ticket = atomicAdd(&g_done, 1u);
        if (ticket == NBLOCKS - 1) {
            int tot = atomicAdd(&g_total, 0);
            const double denom = 48.0 * (double)BB * (double)HW; // 100663296
            out[0] = (float)((double)tot / denom);
            atomicExch(&g_total, 0);      // reset for next graph replay
            atomicExch(&g_done, 0u);
        }
    }
}

extern "C" void kernel_launch(void* const* d_in, const int* in_sizes, int n_in,
                              void* d_out, int out_size) {
    const float* pred = (const float*)d_in[0];
    const float* tgt  = (const float*)d_in[1];
    float* out = (float*)d_out;
    (void)in_sizes; (void)n_in; (void)out_size;

    dim3 bdim(TX, TYW);
    dim3 gdim(WW / TX, HH / TILE_H, BB);
    census_fused<<<gdim, bdim>>>(pred, tgt, out);
}